// round 6
// baseline (speedup 1.0000x reference)
#include <cuda_runtime.h>
#include <cuda_bf16.h>
#include <cstdint>
#include <cstddef>

#define NN 50000
#define EE 800000
#define FF 256
#define LL 3
#define NB 196   // ceil(NN/256)

// ---------------- scratch (device globals) ----------------
__device__ float g_deg[NN];
__device__ float g_dinv[NN];
__device__ int   g_cnt[NN];
__device__ int   g_rowptr[NN + 1];
__device__ int   g_cursor[NN];
__device__ int   g_bsum[NB];
__device__ int   g_boff[NB];
__device__ int   g_csrc[EE];
__device__ float g_cw[EE];
__device__ float g_h[(size_t)NN * FF];
__device__ float g_y[(size_t)NN * FF];
// ping-pong split activation buffers
__device__ __nv_bfloat16 g_Ahi0[(size_t)NN * FF];
__device__ __nv_bfloat16 g_Alo0[(size_t)NN * FF];
__device__ __nv_bfloat16 g_Ahi1[(size_t)NN * FF];
__device__ __nv_bfloat16 g_Alo1[(size_t)NN * FF];
// fused transposed weights: [layer][512][256]; rows 0-255 = Wi^T, 256-511 = Wr^T
__device__ __nv_bfloat16 g_Bhi[3 * 512 * 256];
__device__ __nv_bfloat16 g_Blo[3 * 512 * 256];

// ---------------- helpers ----------------
__device__ __forceinline__ uint32_t smem_u32(const void* p) {
    uint32_t a;
    asm("{ .reg .u64 t; cvta.to.shared.u64 t, %1; cvt.u32.u64 %0, t; }"
        : "=r"(a) : "l"(p));
    return a;
}
__device__ __forceinline__ uint32_t swz(uint32_t off) { return off ^ ((off >> 3) & 0x70); }

__device__ __forceinline__ void ldmx4(uint32_t* r, uint32_t addr) {
    asm volatile("ldmatrix.sync.aligned.m8n8.x4.shared.b16 {%0,%1,%2,%3}, [%4];"
                 : "=r"(r[0]), "=r"(r[1]), "=r"(r[2]), "=r"(r[3]) : "r"(addr));
}
__device__ __forceinline__ void mma16816(float* c, const uint32_t* a, const uint32_t* b) {
    asm volatile(
        "mma.sync.aligned.m16n8k16.row.col.f32.bf16.bf16.f32 "
        "{%0,%1,%2,%3}, {%4,%5,%6,%7}, {%8,%9}, {%0,%1,%2,%3};"
        : "+f"(c[0]), "+f"(c[1]), "+f"(c[2]), "+f"(c[3])
        : "r"(a[0]), "r"(a[1]), "r"(a[2]), "r"(a[3]), "r"(b[0]), "r"(b[1]));
}
__device__ __forceinline__ uint32_t pack_bf16(__nv_bfloat16 a, __nv_bfloat16 b) {
    return (uint32_t)__bfloat16_as_ushort(a) | ((uint32_t)__bfloat16_as_ushort(b) << 16);
}
__device__ __forceinline__ void cp16(uint32_t dst, const void* src, uint32_t valid) {
    asm volatile("cp.async.cg.shared.global [%0], [%1], 16, %2;"
                 :: "r"(dst), "l"(src), "r"(valid ? 16u : 0u));
}
#define CP_COMMIT() asm volatile("cp.async.commit_group;" ::: "memory")
template <int N> __device__ __forceinline__ void cp_wait() {
    asm volatile("cp.async.wait_group %0;" :: "n"(N) : "memory");
}

// ---------------- setup kernels ----------------
__global__ void hist_kernel(const int* __restrict__ src, const int* __restrict__ dst,
                            const float* __restrict__ w) {
    int e = blockIdx.x * blockDim.x + threadIdx.x;
    if (e >= EE) return;
    int d = dst[e];
    atomicAdd(&g_deg[d], w[e]);
    atomicAdd(&g_cnt[d], 1);
}

__global__ void dinv_kernel() {
    int n = blockIdx.x * blockDim.x + threadIdx.x;
    if (n >= NN) return;
    float d = g_deg[n];
    g_dinv[n] = (d > 0.f) ? rsqrtf(d) : 0.f;
}

__global__ void scan_local() {                 // grid NB, 256 thr
    __shared__ int sh[256];
    int b = blockIdx.x, tid = threadIdx.x, i = b * 256 + tid;
    int v = (i < NN) ? g_cnt[i] : 0;
    sh[tid] = v;
    __syncthreads();
    #pragma unroll
    for (int off = 1; off < 256; off <<= 1) {
        int t2 = (tid >= off) ? sh[tid - off] : 0;
        __syncthreads();
        sh[tid] += t2;
        __syncthreads();
    }
    if (i < NN) g_rowptr[i] = sh[tid];          // local inclusive
    if (tid == 255) g_bsum[b] = sh[255];
}
__global__ void scan_blocks() {                 // 1 block, 256 thr
    __shared__ int sh[256];
    int tid = threadIdx.x;
    int v = (tid < NB) ? g_bsum[tid] : 0;
    sh[tid] = v;
    __syncthreads();
    #pragma unroll
    for (int off = 1; off < 256; off <<= 1) {
        int t2 = (tid >= off) ? sh[tid - off] : 0;
        __syncthreads();
        sh[tid] += t2;
        __syncthreads();
    }
    if (tid < NB) g_boff[tid] = sh[tid] - v;    // exclusive
    if (tid == NB - 1) g_rowptr[NN] = sh[tid];  // total
}
__global__ void scan_finish() {                 // grid NB, 256 thr
    int i = blockIdx.x * 256 + threadIdx.x;
    if (i >= NN) return;
    int excl = g_rowptr[i] - g_cnt[i] + g_boff[blockIdx.x];
    g_rowptr[i] = excl;
    g_cursor[i] = excl;
}

__global__ void fill_kernel(const int* __restrict__ src, const int* __restrict__ dst,
                            const float* __restrict__ w) {
    int e = blockIdx.x * blockDim.x + threadIdx.x;
    if (e >= EE) return;
    int s = src[e];
    int d = dst[e];
    int pos = atomicAdd(&g_cursor[d], 1);
    g_csrc[pos] = s;
    g_cw[pos] = g_dinv[s] * w[e] * g_dinv[d];
}

// weights: transpose + split into fused [l][512][256]
__global__ void convert_w_kernel(const float* __restrict__ Wi, const float* __restrict__ Wr) {
    int idx = blockIdx.x * blockDim.x + threadIdx.x;
    if (idx >= 3 * 512 * 256) return;
    int l = idx >> 17;
    int n = (idx >> 8) & 511;
    int k = idx & 255;
    const float* W = (n < 256) ? Wi : Wr;
    int nn = n & 255;
    float v = W[(size_t)l * FF * FF + (size_t)k * FF + nn];
    __nv_bfloat16 hi = __float2bfloat16(v);
    __nv_bfloat16 lo = __float2bfloat16(v - __bfloat162float(hi));
    g_Bhi[idx] = hi;
    g_Blo[idx] = lo;
}

// split layer-0 input activations into buffer 0
__global__ void convert_x_kernel(const float* __restrict__ x) {
    int idx = blockIdx.x * blockDim.x + threadIdx.x;
    if (idx >= NN * FF) return;
    float v = x[idx];
    __nv_bfloat16 hi = __float2bfloat16(v);
    __nv_bfloat16 lo = __float2bfloat16(v - __bfloat162float(hi));
    g_Ahi0[idx] = hi;
    g_Alo0[idx] = lo;
}

// ---------------- HMMA bf16-split fused GEMM (cp.async 2-stage pipeline) ----------------
// Computes column half: ntBase=0 -> H/Y cols 0-127 (nt 0,2); ntBase=1 -> cols 128-255 (nt 1,3).
#define GSM 65536
__global__ __launch_bounds__(256, 2)
void hmma_gemm_kernel(const __nv_bfloat16* __restrict__ Ahi,
                      const __nv_bfloat16* __restrict__ Alo,
                      const __nv_bfloat16* __restrict__ Bhi,
                      const __nv_bfloat16* __restrict__ Blo,
                      const float* __restrict__ bias,
                      float* __restrict__ H, float* __restrict__ Y,
                      int M, int ntBase) {
    extern __shared__ __align__(1024) uint8_t dsm[];
    const uint32_t base = smem_u32(dsm);

    int t = threadIdx.x;
    int lane = t & 31, wid = t >> 5;
    int wm = wid >> 2;        // 0..1
    int wn = wid & 3;         // 0..3
    int row0 = blockIdx.y * 128;
    int nt   = ntBase + 2 * blockIdx.x;   // column tile of fused N=512
    int n0   = nt * 128;

    float acc[4][4][4];
    #pragma unroll
    for (int i = 0; i < 4; i++)
        #pragma unroll
        for (int j = 0; j < 4; j++)
            #pragma unroll
            for (int q = 0; q < 4; q++) acc[i][j][q] = 0.f;

    auto load_chunk = [&](int chunk, int stage) {
        int k0 = chunk * 32;
        uint32_t sA = base + (uint32_t)stage * 32768u;
        uint32_t sB = sA + 16384u;
        #pragma unroll
        for (int u = 0; u < 4; u++) {
            int idx = t + u * 256;            // 0..1023
            int r = idx >> 3;
            int sidx = idx & 7;               // 0-3 hi, 4-7 lo
            uint32_t soff = swz((uint32_t)r * 128 + (uint32_t)sidx * 16);
            int gm = row0 + r;
            const __nv_bfloat16* pa = ((sidx < 4) ? Ahi : Alo)
                + (size_t)(gm < M ? gm : 0) * FF + k0 + (sidx & 3) * 8;
            cp16(sA + soff, pa, (uint32_t)(gm < M));
            const __nv_bfloat16* pb = ((sidx < 4) ? Bhi : Blo)
                + (size_t)(n0 + r) * FF + k0 + (sidx & 3) * 8;
            cp16(sB + soff, pb, 1u);
        }
        CP_COMMIT();
    };

    load_chunk(0, 0);

    for (int c = 0; c < 8; c++) {
        if (c < 7) {
            load_chunk(c + 1, (c + 1) & 1);
            cp_wait<1>();
        } else {
            cp_wait<0>();
        }
        __syncthreads();

        uint32_t aAs = base + (uint32_t)(c & 1) * 32768u;
        uint32_t aBs = aAs + 16384u;

        #pragma unroll
        for (int kk = 0; kk < 2; kk++) {
            uint32_t bh[4][2], bl[4][2];
            #pragma unroll
            for (int fnp = 0; fnp < 2; fnp++) {
                uint32_t brow = (uint32_t)(wn * 32 + fnp * 16 + ((lane >> 4) << 3) + (lane & 7));
                uint32_t bseg = (uint32_t)(kk * 2 + ((lane >> 3) & 1));
                uint32_t tmp[4];
                ldmx4(tmp, aBs + swz(brow * 128 + bseg * 16));
                bh[fnp * 2][0] = tmp[0]; bh[fnp * 2][1] = tmp[1];
                bh[fnp * 2 + 1][0] = tmp[2]; bh[fnp * 2 + 1][1] = tmp[3];
                ldmx4(tmp, aBs + swz(brow * 128 + (4 + bseg) * 16));
                bl[fnp * 2][0] = tmp[0]; bl[fnp * 2][1] = tmp[1];
                bl[fnp * 2 + 1][0] = tmp[2]; bl[fnp * 2 + 1][1] = tmp[3];
            }
            #pragma unroll
            for (int fm = 0; fm < 4; fm++) {
                uint32_t arow = (uint32_t)(wm * 64 + fm * 16 + (lane & 15));
                uint32_t aseg = (uint32_t)(kk * 2 + (lane >> 4));
                uint32_t ah[4], al[4];
                ldmx4(ah, aAs + swz(arow * 128 + aseg * 16));
                ldmx4(al, aAs + swz(arow * 128 + (4 + aseg) * 16));
                #pragma unroll
                for (int fn = 0; fn < 4; fn++) {
                    mma16816(acc[fm][fn], ah, bh[fn]);
                    mma16816(acc[fm][fn], ah, bl[fn]);
                    mma16816(acc[fm][fn], al, bh[fn]);
                }
            }
        }
        __syncthreads();
    }

    // ---- epilogue ----
    bool isY = (nt >= 2);
    float* C = isY ? Y : H;
    int cb = n0 - (isY ? 256 : 0);

    #pragma unroll
    for (int fm = 0; fm < 4; fm++) {
        int m = row0 + wm * 64 + fm * 16 + (lane >> 2);
        #pragma unroll
        for (int fn = 0; fn < 4; fn++) {
            int col = cb + wn * 32 + fn * 8 + (lane & 3) * 2;
            float bx = 0.f, by = 0.f;
            if (isY) {
                float2 b2 = *(const float2*)(bias + col);
                bx = b2.x; by = b2.y;
            }
            if (m < M) {
                float2 v = make_float2(acc[fm][fn][0] + bx, acc[fm][fn][1] + by);
                *(float2*)(C + (size_t)m * FF + col) = v;
            }
            if (m + 8 < M) {
                float2 v = make_float2(acc[fm][fn][2] + bx, acc[fm][fn][3] + by);
                *(float2*)(C + (size_t)(m + 8) * FF + col) = v;
            }
        }
    }
}

// ---------------- aggregation (column half) ----------------
// cols [c0, c0+128): xn[n,f] = relu(y[n,f] + sum_j cw[j]*h[csrc[j],f])
// MODE 0: write bf16 hi/lo split into next A buffers. MODE 1: write fp32 out.
template <int MODE>
__global__ __launch_bounds__(128)
void agg_half_kernel(int c0, float* __restrict__ xnext,
                     __nv_bfloat16* __restrict__ AhiN,
                     __nv_bfloat16* __restrict__ AloN) {
    int n = blockIdx.x * 4 + (threadIdx.x >> 5);
    if (n >= NN) return;
    int f = c0 + (threadIdx.x & 31) * 4;

    float4 acc = *(const float4*)(g_y + (size_t)n * FF + f);
    int j = g_rowptr[n], end = g_rowptr[n + 1];

    for (; j + 4 <= end; j += 4) {
        int s0 = g_csrc[j], s1 = g_csrc[j + 1], s2 = g_csrc[j + 2], s3 = g_csrc[j + 3];
        float w0 = g_cw[j], w1 = g_cw[j + 1], w2 = g_cw[j + 2], w3 = g_cw[j + 3];
        float4 h0 = *(const float4*)(g_h + (size_t)s0 * FF + f);
        float4 h1 = *(const float4*)(g_h + (size_t)s1 * FF + f);
        float4 h2 = *(const float4*)(g_h + (size_t)s2 * FF + f);
        float4 h3 = *(const float4*)(g_h + (size_t)s3 * FF + f);
        acc.x = fmaf(w0, h0.x, fmaf(w1, h1.x, fmaf(w2, h2.x, fmaf(w3, h3.x, acc.x))));
        acc.y = fmaf(w0, h0.y, fmaf(w1, h1.y, fmaf(w2, h2.y, fmaf(w3, h3.y, acc.y))));
        acc.z = fmaf(w0, h0.z, fmaf(w1, h1.z, fmaf(w2, h2.z, fmaf(w3, h3.z, acc.z))));
        acc.w = fmaf(w0, h0.w, fmaf(w1, h1.w, fmaf(w2, h2.w, fmaf(w3, h3.w, acc.w))));
    }
    for (; j < end; j++) {
        int s0 = g_csrc[j];
        float w0 = g_cw[j];
        float4 h0 = *(const float4*)(g_h + (size_t)s0 * FF + f);
        acc.x = fmaf(w0, h0.x, acc.x);
        acc.y = fmaf(w0, h0.y, acc.y);
        acc.z = fmaf(w0, h0.z, acc.z);
        acc.w = fmaf(w0, h0.w, acc.w);
    }
    acc.x = fmaxf(acc.x, 0.f);
    acc.y = fmaxf(acc.y, 0.f);
    acc.z = fmaxf(acc.z, 0.f);
    acc.w = fmaxf(acc.w, 0.f);

    if (MODE == 1) {
        *(float4*)(xnext + (size_t)n * FF + f) = acc;
    } else {
        __nv_bfloat16 h0 = __float2bfloat16(acc.x);
        __nv_bfloat16 h1 = __float2bfloat16(acc.y);
        __nv_bfloat16 h2 = __float2bfloat16(acc.z);
        __nv_bfloat16 h3 = __float2bfloat16(acc.w);
        __nv_bfloat16 l0 = __float2bfloat16(acc.x - __bfloat162float(h0));
        __nv_bfloat16 l1 = __float2bfloat16(acc.y - __bfloat162float(h1));
        __nv_bfloat16 l2 = __float2bfloat16(acc.z - __bfloat162float(h2));
        __nv_bfloat16 l3 = __float2bfloat16(acc.w - __bfloat162float(h3));
        uint2 hp = make_uint2(pack_bf16(h0, h1), pack_bf16(h2, h3));
        uint2 lp = make_uint2(pack_bf16(l0, l1), pack_bf16(l2, l3));
        *(uint2*)(AhiN + (size_t)n * FF + f) = hp;
        *(uint2*)(AloN + (size_t)n * FF + f) = lp;
    }
}

// ---------------- launch ----------------
extern "C" void kernel_launch(void* const* d_in, const int* in_sizes, int n_in,
                              void* d_out, int out_size) {
    const float* x    = (const float*)d_in[0];
    const int*   ei   = (const int*)d_in[1];
    const float* w    = (const float*)d_in[2];
    const float* Wi   = (const float*)d_in[3];
    const float* Wr   = (const float*)d_in[4];
    const float* bias = (const float*)d_in[5];
    float* out = (float*)d_out;

    const int* src = ei;
    const int* dst = ei + EE;

    void *p_deg, *p_cnt, *p_h, *p_y, *p_Bhi, *p_Blo;
    void *p_Ahi0, *p_Alo0, *p_Ahi1, *p_Alo1;
    cudaGetSymbolAddress(&p_deg,  g_deg);
    cudaGetSymbolAddress(&p_cnt,  g_cnt);
    cudaGetSymbolAddress(&p_h,    g_h);
    cudaGetSymbolAddress(&p_y,    g_y);
    cudaGetSymbolAddress(&p_Ahi0, g_Ahi0);
    cudaGetSymbolAddress(&p_Alo0, g_Alo0);
    cudaGetSymbolAddress(&p_Ahi1, g_Ahi1);
    cudaGetSymbolAddress(&p_Alo1, g_Alo1);
    cudaGetSymbolAddress(&p_Bhi,  g_Bhi);
    cudaGetSymbolAddress(&p_Blo,  g_Blo);

    static cudaStream_t s2 = nullptr;
    static cudaEvent_t evFork = nullptr, evW = nullptr;
    static cudaEvent_t evA[LL], evB[LL], evDone[LL];
    if (!s2) {
        cudaStreamCreateWithFlags(&s2, cudaStreamNonBlocking);
        cudaEventCreateWithFlags(&evFork, cudaEventDisableTiming);
        cudaEventCreateWithFlags(&evW, cudaEventDisableTiming);
        for (int l = 0; l < LL; l++) {
            cudaEventCreateWithFlags(&evA[l], cudaEventDisableTiming);
            cudaEventCreateWithFlags(&evB[l], cudaEventDisableTiming);
            cudaEventCreateWithFlags(&evDone[l], cudaEventDisableTiming);
        }
        cudaFuncSetAttribute(hmma_gemm_kernel,
                             cudaFuncAttributeMaxDynamicSharedMemorySize, GSM);
    }

    // ---- fork side stream: weight convert + CSR setup chain ----
    cudaEventRecord(evFork, 0);
    cudaStreamWaitEvent(s2, evFork, 0);
    convert_w_kernel<<<(3 * 512 * 256 + 255) / 256, 256, 0, s2>>>(Wi, Wr);
    cudaEventRecord(evW, s2);
    cudaMemsetAsync(p_deg, 0, NN * sizeof(float), s2);
    cudaMemsetAsync(p_cnt, 0, NN * sizeof(int), s2);
    hist_kernel<<<(EE + 255) / 256, 256, 0, s2>>>(src, dst, w);
    dinv_kernel<<<(NN + 255) / 256, 256, 0, s2>>>();
    scan_local<<<NB, 256, 0, s2>>>();
    scan_blocks<<<1, 256, 0, s2>>>();
    scan_finish<<<NB, 256, 0, s2>>>();
    fill_kernel<<<(EE + 255) / 256, 256, 0, s2>>>(src, dst, w);

    // ---- main: split layer-0 activations ----
    convert_x_kernel<<<(NN * FF + 255) / 256, 256>>>(x);
    cudaStreamWaitEvent(0, evW, 0);

    dim3 ggrid(2, (NN + 127) / 128);
    const int agg_grid = (NN + 3) / 4;

    __nv_bfloat16* AhiBuf[2] = { (__nv_bfloat16*)p_Ahi0, (__nv_bfloat16*)p_Ahi1 };
    __nv_bfloat16* AloBuf[2] = { (__nv_bfloat16*)p_Alo0, (__nv_bfloat16*)p_Alo1 };
    const __nv_bfloat16* Bhi = (const __nv_bfloat16*)p_Bhi;
    const __nv_bfloat16* Blo = (const __nv_bfloat16*)p_Blo;

    for (int l = 0; l < LL; l++) {
        const float* bl = bias + (size_t)l * FF;
        const __nv_bfloat16* Ahi = AhiBuf[l & 1];
        const __nv_bfloat16* Alo = AloBuf[l & 1];
        __nv_bfloat16* AhiN = AhiBuf[(l + 1) & 1];
        __nv_bfloat16* AloN = AloBuf[(l + 1) & 1];
        const __nv_bfloat16* Bh = Bhi + (size_t)l * 512 * 256;
        const __nv_bfloat16* Bl = Blo + (size_t)l * 512 * 256;

        if (l > 0) cudaStreamWaitEvent(0, evDone[l - 1], 0);  // A buffer fully written

        // main stream: two column-half GEMMs
        hmma_gemm_kernel<<<ggrid, 256, GSM>>>(Ahi, Alo, Bh, Bl, bl,
                                              (float*)p_h, (float*)p_y, NN, 0);
        cudaEventRecord(evA[l], 0);
        hmma_gemm_kernel<<<ggrid, 256, GSM>>>(Ahi, Alo, Bh, Bl, bl,
                                              (float*)p_h, (float*)p_y, NN, 1);
        cudaEventRecord(evB[l], 0);

        // side stream: aggregation halves (CSR chain already ordered on s2)
        cudaStreamWaitEvent(s2, evA[l], 0);
        if (l < LL - 1)
            agg_half_kernel<0><<<agg_grid, 128, 0, s2>>>(0, nullptr, AhiN, AloN);
        else
            agg_half_kernel<1><<<agg_grid, 128, 0, s2>>>(0, out, nullptr, nullptr);
        cudaStreamWaitEvent(s2, evB[l], 0);
        if (l < LL - 1)
            agg_half_kernel<0><<<agg_grid, 128, 0, s2>>>(128, nullptr, AhiN, AloN);
        else
            agg_half_kernel<1><<<agg_grid, 128, 0, s2>>>(128, out, nullptr, nullptr);
        cudaEventRecord(evDone[l], s2);
    }

    // join side stream back before capture ends
    cudaStreamWaitEvent(0, evDone[LL - 1], 0);
}

// round 7
// speedup vs baseline: 1.0981x; 1.0981x over previous
#include <cuda_runtime.h>
#include <cuda_bf16.h>
#include <cuda_fp16.h>
#include <cstdint>
#include <cstddef>

#define NN 50000
#define EE 800000
#define FF 256
#define LL 3
#define NB 196   // ceil(NN/256)

// ---------------- scratch (device globals) ----------------
__device__ float g_deg[NN];
__device__ float g_dinv[NN];
__device__ int   g_cnt[NN];
__device__ int   g_rowptr[NN + 1];
__device__ int   g_cursor[NN];
__device__ int   g_bsum[NB];
__device__ int   g_boff[NB];
__device__ int   g_csrc[EE];
__device__ float g_cw[EE];
__device__ __half g_h[(size_t)NN * FF];      // fp16 aggregation operand
__device__ float  g_y[(size_t)NN * FF];      // fp32 root term
__device__ __nv_bfloat16 g_Ahi[(size_t)NN * FF];
__device__ __nv_bfloat16 g_Alo[(size_t)NN * FF];
// fused transposed weights: [layer][512][256]; rows 0-255 = Wi^T, 256-511 = Wr^T
__device__ __nv_bfloat16 g_Bhi[3 * 512 * 256];
__device__ __nv_bfloat16 g_Blo[3 * 512 * 256];

// ---------------- helpers ----------------
__device__ __forceinline__ uint32_t smem_u32(const void* p) {
    uint32_t a;
    asm("{ .reg .u64 t; cvta.to.shared.u64 t, %1; cvt.u32.u64 %0, t; }"
        : "=r"(a) : "l"(p));
    return a;
}
__device__ __forceinline__ uint32_t swz(uint32_t off) { return off ^ ((off >> 3) & 0x70); }

__device__ __forceinline__ void ldmx4(uint32_t* r, uint32_t addr) {
    asm volatile("ldmatrix.sync.aligned.m8n8.x4.shared.b16 {%0,%1,%2,%3}, [%4];"
                 : "=r"(r[0]), "=r"(r[1]), "=r"(r[2]), "=r"(r[3]) : "r"(addr));
}
__device__ __forceinline__ void mma16816(float* c, const uint32_t* a, const uint32_t* b) {
    asm volatile(
        "mma.sync.aligned.m16n8k16.row.col.f32.bf16.bf16.f32 "
        "{%0,%1,%2,%3}, {%4,%5,%6,%7}, {%8,%9}, {%0,%1,%2,%3};"
        : "+f"(c[0]), "+f"(c[1]), "+f"(c[2]), "+f"(c[3])
        : "r"(a[0]), "r"(a[1]), "r"(a[2]), "r"(a[3]), "r"(b[0]), "r"(b[1]));
}
__device__ __forceinline__ uint32_t pack_bf16(__nv_bfloat16 a, __nv_bfloat16 b) {
    return (uint32_t)__bfloat16_as_ushort(a) | ((uint32_t)__bfloat16_as_ushort(b) << 16);
}
__device__ __forceinline__ void cp16(uint32_t dst, const void* src, uint32_t valid) {
    asm volatile("cp.async.cg.shared.global [%0], [%1], 16, %2;"
                 :: "r"(dst), "l"(src), "r"(valid ? 16u : 0u));
}
#define CP_COMMIT() asm volatile("cp.async.commit_group;" ::: "memory")
template <int N> __device__ __forceinline__ void cp_wait() {
    asm volatile("cp.async.wait_group %0;" :: "n"(N) : "memory");
}

// ---------------- setup kernels ----------------
__global__ void hist_kernel(const int* __restrict__ src, const int* __restrict__ dst,
                            const float* __restrict__ w) {
    int e = blockIdx.x * blockDim.x + threadIdx.x;
    if (e >= EE) return;
    int d = dst[e];
    atomicAdd(&g_deg[d], w[e]);
    atomicAdd(&g_cnt[d], 1);
}

__global__ void dinv_kernel() {
    int n = blockIdx.x * blockDim.x + threadIdx.x;
    if (n >= NN) return;
    float d = g_deg[n];
    g_dinv[n] = (d > 0.f) ? rsqrtf(d) : 0.f;
}

__global__ void scan_local() {
    __shared__ int sh[256];
    int b = blockIdx.x, tid = threadIdx.x, i = b * 256 + tid;
    int v = (i < NN) ? g_cnt[i] : 0;
    sh[tid] = v;
    __syncthreads();
    #pragma unroll
    for (int off = 1; off < 256; off <<= 1) {
        int t2 = (tid >= off) ? sh[tid - off] : 0;
        __syncthreads();
        sh[tid] += t2;
        __syncthreads();
    }
    if (i < NN) g_rowptr[i] = sh[tid];
    if (tid == 255) g_bsum[b] = sh[255];
}
__global__ void scan_blocks() {
    __shared__ int sh[256];
    int tid = threadIdx.x;
    int v = (tid < NB) ? g_bsum[tid] : 0;
    sh[tid] = v;
    __syncthreads();
    #pragma unroll
    for (int off = 1; off < 256; off <<= 1) {
        int t2 = (tid >= off) ? sh[tid - off] : 0;
        __syncthreads();
        sh[tid] += t2;
        __syncthreads();
    }
    if (tid < NB) g_boff[tid] = sh[tid] - v;
    if (tid == NB - 1) g_rowptr[NN] = sh[tid];
}
__global__ void scan_finish() {
    int i = blockIdx.x * 256 + threadIdx.x;
    if (i >= NN) return;
    int excl = g_rowptr[i] - g_cnt[i] + g_boff[blockIdx.x];
    g_rowptr[i] = excl;
    g_cursor[i] = excl;
}

__global__ void fill_kernel(const int* __restrict__ src, const int* __restrict__ dst,
                            const float* __restrict__ w) {
    int e = blockIdx.x * blockDim.x + threadIdx.x;
    if (e >= EE) return;
    int s = src[e];
    int d = dst[e];
    int pos = atomicAdd(&g_cursor[d], 1);
    g_csrc[pos] = s;
    g_cw[pos] = g_dinv[s] * w[e] * g_dinv[d];
}

__global__ void convert_w_kernel(const float* __restrict__ Wi, const float* __restrict__ Wr) {
    int idx = blockIdx.x * blockDim.x + threadIdx.x;
    if (idx >= 3 * 512 * 256) return;
    int l = idx >> 17;
    int n = (idx >> 8) & 511;
    int k = idx & 255;
    const float* W = (n < 256) ? Wi : Wr;
    int nn = n & 255;
    float v = W[(size_t)l * FF * FF + (size_t)k * FF + nn];
    __nv_bfloat16 hi = __float2bfloat16(v);
    __nv_bfloat16 lo = __float2bfloat16(v - __bfloat162float(hi));
    g_Bhi[idx] = hi;
    g_Blo[idx] = lo;
}

__global__ void convert_x_kernel(const float* __restrict__ x) {
    int idx = blockIdx.x * blockDim.x + threadIdx.x;
    if (idx >= NN * FF) return;
    float v = x[idx];
    __nv_bfloat16 hi = __float2bfloat16(v);
    __nv_bfloat16 lo = __float2bfloat16(v - __bfloat162float(hi));
    g_Ahi[idx] = hi;
    g_Alo[idx] = lo;
}

// ---------------- HMMA bf16-split fused GEMM (cp.async 2-stage pipeline) ----------------
// [H(fp16) | Y(fp32)+bias] = A[M,256] @ Bfused[512,256]^T
#define GSM 65536
__global__ __launch_bounds__(256, 2)
void hmma_gemm_kernel(const __nv_bfloat16* __restrict__ Ahi,
                      const __nv_bfloat16* __restrict__ Alo,
                      const __nv_bfloat16* __restrict__ Bhi,
                      const __nv_bfloat16* __restrict__ Blo,
                      const float* __restrict__ bias,
                      __half* __restrict__ H, float* __restrict__ Y, int M) {
    extern __shared__ __align__(1024) uint8_t dsm[];
    const uint32_t base = smem_u32(dsm);

    int t = threadIdx.x;
    int lane = t & 31, wid = t >> 5;
    int wm = wid >> 2;        // 0..1
    int wn = wid & 3;         // 0..3
    int row0 = blockIdx.y * 128;
    int nt   = blockIdx.x;    // 0..3 over fused N=512
    int n0   = nt * 128;

    float acc[4][4][4];
    #pragma unroll
    for (int i = 0; i < 4; i++)
        #pragma unroll
        for (int j = 0; j < 4; j++)
            #pragma unroll
            for (int q = 0; q < 4; q++) acc[i][j][q] = 0.f;

    auto load_chunk = [&](int chunk, int stage) {
        int k0 = chunk * 32;
        uint32_t sA = base + (uint32_t)stage * 32768u;
        uint32_t sB = sA + 16384u;
        #pragma unroll
        for (int u = 0; u < 4; u++) {
            int idx = t + u * 256;
            int r = idx >> 3;
            int sidx = idx & 7;               // 0-3 hi, 4-7 lo
            uint32_t soff = swz((uint32_t)r * 128 + (uint32_t)sidx * 16);
            int gm = row0 + r;
            const __nv_bfloat16* pa = ((sidx < 4) ? Ahi : Alo)
                + (size_t)(gm < M ? gm : 0) * FF + k0 + (sidx & 3) * 8;
            cp16(sA + soff, pa, (uint32_t)(gm < M));
            const __nv_bfloat16* pb = ((sidx < 4) ? Bhi : Blo)
                + (size_t)(n0 + r) * FF + k0 + (sidx & 3) * 8;
            cp16(sB + soff, pb, 1u);
        }
        CP_COMMIT();
    };

    load_chunk(0, 0);

    for (int c = 0; c < 8; c++) {
        if (c < 7) {
            load_chunk(c + 1, (c + 1) & 1);
            cp_wait<1>();
        } else {
            cp_wait<0>();
        }
        __syncthreads();

        uint32_t aAs = base + (uint32_t)(c & 1) * 32768u;
        uint32_t aBs = aAs + 16384u;

        #pragma unroll
        for (int kk = 0; kk < 2; kk++) {
            uint32_t bh[4][2], bl[4][2];
            #pragma unroll
            for (int fnp = 0; fnp < 2; fnp++) {
                uint32_t brow = (uint32_t)(wn * 32 + fnp * 16 + ((lane >> 4) << 3) + (lane & 7));
                uint32_t bseg = (uint32_t)(kk * 2 + ((lane >> 3) & 1));
                uint32_t tmp[4];
                ldmx4(tmp, aBs + swz(brow * 128 + bseg * 16));
                bh[fnp * 2][0] = tmp[0]; bh[fnp * 2][1] = tmp[1];
                bh[fnp * 2 + 1][0] = tmp[2]; bh[fnp * 2 + 1][1] = tmp[3];
                ldmx4(tmp, aBs + swz(brow * 128 + (4 + bseg) * 16));
                bl[fnp * 2][0] = tmp[0]; bl[fnp * 2][1] = tmp[1];
                bl[fnp * 2 + 1][0] = tmp[2]; bl[fnp * 2 + 1][1] = tmp[3];
            }
            #pragma unroll
            for (int fm = 0; fm < 4; fm++) {
                uint32_t arow = (uint32_t)(wm * 64 + fm * 16 + (lane & 15));
                uint32_t aseg = (uint32_t)(kk * 2 + (lane >> 4));
                uint32_t ah[4], al[4];
                ldmx4(ah, aAs + swz(arow * 128 + aseg * 16));
                ldmx4(al, aAs + swz(arow * 128 + (4 + aseg) * 16));
                #pragma unroll
                for (int fn = 0; fn < 4; fn++) {
                    mma16816(acc[fm][fn], ah, bh[fn]);
                    mma16816(acc[fm][fn], ah, bl[fn]);
                    mma16816(acc[fm][fn], al, bh[fn]);
                }
            }
        }
        __syncthreads();
    }

    // ---- epilogue ----
    bool isY = (nt >= 2);
    int cb = n0 - (isY ? 256 : 0);

    #pragma unroll
    for (int fm = 0; fm < 4; fm++) {
        int m = row0 + wm * 64 + fm * 16 + (lane >> 2);
        #pragma unroll
        for (int fn = 0; fn < 4; fn++) {
            int col = cb + wn * 32 + fn * 8 + (lane & 3) * 2;
            if (isY) {
                float2 b2 = *(const float2*)(bias + col);
                if (m < M) {
                    float2 v = make_float2(acc[fm][fn][0] + b2.x, acc[fm][fn][1] + b2.y);
                    *(float2*)(Y + (size_t)m * FF + col) = v;
                }
                if (m + 8 < M) {
                    float2 v = make_float2(acc[fm][fn][2] + b2.x, acc[fm][fn][3] + b2.y);
                    *(float2*)(Y + (size_t)(m + 8) * FF + col) = v;
                }
            } else {
                if (m < M) {
                    __half2 v = __floats2half2_rn(acc[fm][fn][0], acc[fm][fn][1]);
                    *(__half2*)(H + (size_t)m * FF + col) = v;
                }
                if (m + 8 < M) {
                    __half2 v = __floats2half2_rn(acc[fm][fn][2], acc[fm][fn][3]);
                    *(__half2*)(H + (size_t)(m + 8) * FF + col) = v;
                }
            }
        }
    }
}

// ---------------- aggregation ----------------
// xnext[n,f] = relu(y[n,f] + sum_j cw[j]*h[csrc[j],f]), h in fp16
// MODE 0: write bf16 hi/lo split (next GEMM A). MODE 1: write fp32 out.
template <int MODE>
__global__ __launch_bounds__(128)
void agg_kernel(float* __restrict__ xnext) {
    int n = blockIdx.x * 2 + (threadIdx.x >> 6);
    if (n >= NN) return;
    int f = (threadIdx.x & 63) * 4;

    float4 acc = *(const float4*)(g_y + (size_t)n * FF + f);
    int j = g_rowptr[n], end = g_rowptr[n + 1];

    auto fetch = [&](int s) -> float4 {
        uint2 raw = *(const uint2*)(g_h + (size_t)s * FF + f);
        float2 ab = __half22float2(*(__half2*)&raw.x);
        float2 cd = __half22float2(*(__half2*)&raw.y);
        return make_float4(ab.x, ab.y, cd.x, cd.y);
    };

    for (; j + 4 <= end; j += 4) {
        int s0 = g_csrc[j], s1 = g_csrc[j + 1], s2 = g_csrc[j + 2], s3 = g_csrc[j + 3];
        float w0 = g_cw[j], w1 = g_cw[j + 1], w2 = g_cw[j + 2], w3 = g_cw[j + 3];
        float4 h0 = fetch(s0);
        float4 h1 = fetch(s1);
        float4 h2 = fetch(s2);
        float4 h3 = fetch(s3);
        acc.x = fmaf(w0, h0.x, fmaf(w1, h1.x, fmaf(w2, h2.x, fmaf(w3, h3.x, acc.x))));
        acc.y = fmaf(w0, h0.y, fmaf(w1, h1.y, fmaf(w2, h2.y, fmaf(w3, h3.y, acc.y))));
        acc.z = fmaf(w0, h0.z, fmaf(w1, h1.z, fmaf(w2, h2.z, fmaf(w3, h3.z, acc.z))));
        acc.w = fmaf(w0, h0.w, fmaf(w1, h1.w, fmaf(w2, h2.w, fmaf(w3, h3.w, acc.w))));
    }
    for (; j < end; j++) {
        float w0 = g_cw[j];
        float4 h0 = fetch(g_csrc[j]);
        acc.x = fmaf(w0, h0.x, acc.x);
        acc.y = fmaf(w0, h0.y, acc.y);
        acc.z = fmaf(w0, h0.z, acc.z);
        acc.w = fmaf(w0, h0.w, acc.w);
    }
    acc.x = fmaxf(acc.x, 0.f);
    acc.y = fmaxf(acc.y, 0.f);
    acc.z = fmaxf(acc.z, 0.f);
    acc.w = fmaxf(acc.w, 0.f);

    if (MODE == 1) {
        *(float4*)(xnext + (size_t)n * FF + f) = acc;
    } else {
        __nv_bfloat16 h0 = __float2bfloat16(acc.x);
        __nv_bfloat16 h1 = __float2bfloat16(acc.y);
        __nv_bfloat16 h2 = __float2bfloat16(acc.z);
        __nv_bfloat16 h3 = __float2bfloat16(acc.w);
        __nv_bfloat16 l0 = __float2bfloat16(acc.x - __bfloat162float(h0));
        __nv_bfloat16 l1 = __float2bfloat16(acc.y - __bfloat162float(h1));
        __nv_bfloat16 l2 = __float2bfloat16(acc.z - __bfloat162float(h2));
        __nv_bfloat16 l3 = __float2bfloat16(acc.w - __bfloat162float(h3));
        uint2 hp = make_uint2(pack_bf16(h0, h1), pack_bf16(h2, h3));
        uint2 lp = make_uint2(pack_bf16(l0, l1), pack_bf16(l2, l3));
        *(uint2*)(g_Ahi + (size_t)n * FF + f) = hp;
        *(uint2*)(g_Alo + (size_t)n * FF + f) = lp;
    }
}

// ---------------- launch ----------------
extern "C" void kernel_launch(void* const* d_in, const int* in_sizes, int n_in,
                              void* d_out, int out_size) {
    const float* x    = (const float*)d_in[0];
    const int*   ei   = (const int*)d_in[1];
    const float* w    = (const float*)d_in[2];
    const float* Wi   = (const float*)d_in[3];
    const float* Wr   = (const float*)d_in[4];
    const float* bias = (const float*)d_in[5];
    float* out = (float*)d_out;

    const int* src = ei;
    const int* dst = ei + EE;

    void *p_deg, *p_cnt, *p_h, *p_y, *p_Ahi, *p_Alo, *p_Bhi, *p_Blo;
    cudaGetSymbolAddress(&p_deg, g_deg);
    cudaGetSymbolAddress(&p_cnt, g_cnt);
    cudaGetSymbolAddress(&p_h,   g_h);
    cudaGetSymbolAddress(&p_y,   g_y);
    cudaGetSymbolAddress(&p_Ahi, g_Ahi);
    cudaGetSymbolAddress(&p_Alo, g_Alo);
    cudaGetSymbolAddress(&p_Bhi, g_Bhi);
    cudaGetSymbolAddress(&p_Blo, g_Blo);

    static cudaStream_t s2 = nullptr;
    static cudaEvent_t evFork = nullptr, evW = nullptr, evJoin = nullptr;
    if (!s2) {
        cudaStreamCreateWithFlags(&s2, cudaStreamNonBlocking);
        cudaEventCreateWithFlags(&evFork, cudaEventDisableTiming);
        cudaEventCreateWithFlags(&evW, cudaEventDisableTiming);
        cudaEventCreateWithFlags(&evJoin, cudaEventDisableTiming);
        cudaFuncSetAttribute(hmma_gemm_kernel,
                             cudaFuncAttributeMaxDynamicSharedMemorySize, GSM);
    }

    // ---- fork: weight convert + CSR setup chain on side stream ----
    cudaEventRecord(evFork, 0);
    cudaStreamWaitEvent(s2, evFork, 0);
    convert_w_kernel<<<(3 * 512 * 256 + 255) / 256, 256, 0, s2>>>(Wi, Wr);
    cudaEventRecord(evW, s2);
    cudaMemsetAsync(p_deg, 0, NN * sizeof(float), s2);
    cudaMemsetAsync(p_cnt, 0, NN * sizeof(int), s2);
    hist_kernel<<<(EE + 255) / 256, 256, 0, s2>>>(src, dst, w);
    dinv_kernel<<<(NN + 255) / 256, 256, 0, s2>>>();
    scan_local<<<NB, 256, 0, s2>>>();
    scan_blocks<<<1, 256, 0, s2>>>();
    scan_finish<<<NB, 256, 0, s2>>>();
    fill_kernel<<<(EE + 255) / 256, 256, 0, s2>>>(src, dst, w);
    cudaEventRecord(evJoin, s2);

    // ---- main: split layer-0 activations ----
    convert_x_kernel<<<(NN * FF + 255) / 256, 256>>>(x);
    cudaStreamWaitEvent(0, evW, 0);

    dim3 ggrid(4, (NN + 127) / 128);
    const __nv_bfloat16* Ahi = (const __nv_bfloat16*)p_Ahi;
    const __nv_bfloat16* Alo = (const __nv_bfloat16*)p_Alo;
    const __nv_bfloat16* Bhi = (const __nv_bfloat16*)p_Bhi;
    const __nv_bfloat16* Blo = (const __nv_bfloat16*)p_Blo;

    for (int l = 0; l < LL; l++) {
        const float* bl = bias + (size_t)l * FF;

        hmma_gemm_kernel<<<ggrid, 256, GSM>>>(Ahi, Alo,
                                              Bhi + (size_t)l * 512 * 256,
                                              Blo + (size_t)l * 512 * 256,
                                              bl, (__half*)p_h, (float*)p_y, NN);
        if (l == 0) cudaStreamWaitEvent(0, evJoin, 0);   // CSR ready before first agg
        if (l < LL - 1)
            agg_kernel<0><<<(NN + 1) / 2, 128>>>(nullptr);
        else
            agg_kernel<1><<<(NN + 1) / 2, 128>>>(out);
    }
}